// round 1
// baseline (speedup 1.0000x reference)
#include <cuda_runtime.h>
#include <cstdint>

#define DD 1024          // bond dimension
#define NCTA 128
#define NTHREADS 256
#define CPC (DD / NCTA)  // columns per CTA = 8
#define FMAX 1024

// Persistent state (no allocs allowed)
__device__ float g_v[2][DD];
__device__ unsigned g_count = 0;
__device__ unsigned g_gen = 0;

__device__ __forceinline__ void grid_barrier() {
    __syncthreads();
    if (threadIdx.x == 0) {
        __threadfence();
        unsigned gen = *((volatile unsigned*)&g_gen);
        unsigned t = atomicAdd(&g_count, 1u);
        if (t == NCTA - 1) {
            atomicExch(&g_count, 0u);
            __threadfence();
            atomicAdd(&g_gen, 1u);
        } else {
            while (*((volatile unsigned*)&g_gen) == gen) { }
        }
        __threadfence();
    }
    __syncthreads();
}

__global__ __launch_bounds__(NTHREADS, 1)
void tn_chain_kernel(const int* __restrict__ x,
                     const float* __restrict__ core,
                     const float* __restrict__ left,
                     const float* __restrict__ right,
                     float* __restrict__ out,
                     int F) {
    __shared__ float sh_v[DD];
    __shared__ int   sh_x[FMAX];
    __shared__ float sh_p[8][CPC];
    __shared__ float sh_r[8];

    const int tid  = threadIdx.x;
    const int w    = tid >> 5;
    const int lane = tid & 31;
    const int c    = lane & (CPC - 1);   // column within CTA (0..7)
    const int roff = lane >> 3;          // row offset (0..3)
    const int col  = blockIdx.x * CPC + c;

    for (int i = tid; i < F; i += NTHREADS) sh_x[i] = x[i];
    __syncthreads();

    for (int s = 0; s < F; ++s) {
        const float* vsrc = (s == 0) ? left : g_v[(s + 1) & 1];
        // stage v into shared (L2 loads; bypass L1 — stale across barrier)
        #pragma unroll
        for (int k = 0; k < DD / NTHREADS; ++k)
            sh_v[tid + k * NTHREADS] = __ldcg(vsrc + tid + k * NTHREADS);
        __syncthreads();

        const float* M = core + (size_t)sh_x[s] * (DD * DD) + col;
        float acc = 0.f;
        const int i0 = w * (DD / 8) + roff;   // warp w owns rows [w*128, w*128+128)
        #pragma unroll 8
        for (int it = 0; it < 32; ++it) {
            int i = i0 + it * 4;
            acc += sh_v[i] * __ldg(M + (size_t)i * DD);
        }
        // reduce across the 4 row-offsets within the warp (lanes differing by 8,16)
        acc += __shfl_xor_sync(0xffffffffu, acc, 8);
        acc += __shfl_xor_sync(0xffffffffu, acc, 16);
        if (lane < CPC) sh_p[w][lane] = acc;
        __syncthreads();
        if (tid < CPC) {
            float y = 0.f;
            #pragma unroll
            for (int ww = 0; ww < 8; ++ww) y += sh_p[ww][tid];
            g_v[s & 1][blockIdx.x * CPC + tid] = y;
        }
        grid_barrier();
    }

    // Final dot: CTA 0 only, deterministic reduction
    if (blockIdx.x == 0) {
        const float* vf = g_v[(F - 1) & 1];
        float part = 0.f;
        #pragma unroll
        for (int k = 0; k < DD / NTHREADS; ++k) {
            int i = tid + k * NTHREADS;
            part += __ldcg(vf + i) * right[i];
        }
        part += __shfl_xor_sync(0xffffffffu, part, 16);
        part += __shfl_xor_sync(0xffffffffu, part, 8);
        part += __shfl_xor_sync(0xffffffffu, part, 4);
        part += __shfl_xor_sync(0xffffffffu, part, 2);
        part += __shfl_xor_sync(0xffffffffu, part, 1);
        if (lane == 0) sh_r[w] = part;
        __syncthreads();
        if (tid == 0) {
            float tot = 0.f;
            #pragma unroll
            for (int ww = 0; ww < 8; ++ww) tot += sh_r[ww];
            out[0] = tot;
        }
    }
}

extern "C" void kernel_launch(void* const* d_in, const int* in_sizes, int n_in,
                              void* d_out, int out_size) {
    const int*   x     = (const int*)d_in[0];
    const float* core  = (const float*)d_in[1];
    const float* left  = (const float*)d_in[2];
    const float* right = (const float*)d_in[3];
    float* out = (float*)d_out;
    int F = in_sizes[0];

    tn_chain_kernel<<<NCTA, NTHREADS>>>(x, core, left, right, out, F);
}

// round 2
// speedup vs baseline: 1.4935x; 1.4935x over previous
#include <cuda_runtime.h>
#include <cstdint>

#define DD 1024
#define NCTA 128
#define NTHREADS 1024
#define FMAX 1024

// Persistent state (no allocs allowed)
// g_vp[buf][row_quarter][col]: partial sums of v for next step
__device__ float g_vp[2][4][DD];
__device__ unsigned g_count = 0;
__device__ unsigned g_gen = 0;

__device__ __forceinline__ void grid_barrier() {
    __syncthreads();
    if (threadIdx.x == 0) {
        unsigned gen = *((volatile unsigned*)&g_gen);
        unsigned t = atomicAdd(&g_count, 1u);
        if (t == NCTA - 1) {
            atomicExch(&g_count, 0u);
            __threadfence();
            atomicAdd(&g_gen, 1u);
        } else {
            while (*((volatile unsigned*)&g_gen) == gen) { }
        }
        __threadfence();
    }
    __syncthreads();
}

__global__ __launch_bounds__(NTHREADS, 1)
void tn_chain_kernel(const int* __restrict__ x,
                     const float* __restrict__ core,
                     const float* __restrict__ left,
                     const float* __restrict__ right,
                     float* __restrict__ out,
                     int F) {
    __shared__ float sh_v[256];        // this CTA's 256-row slice of v
    __shared__ int   sh_x[FMAX];
    __shared__ float sh_p[32][32];     // [warp][col-in-block] partials
    __shared__ float sh_r[32];

    const int tid  = threadIdx.x;
    const int w    = tid >> 5;
    const int lane = tid & 31;
    const int cb   = blockIdx.x >> 2;      // column block (0..31), 32 cols
    const int rb   = blockIdx.x & 3;       // row quarter (0..3), 256 rows
    const int col  = cb * 32 + lane;       // global output column
    const int row_base = rb * 256 + w * 8; // this thread's 8 rows start here

    for (int i = tid; i < F; i += NTHREADS) sh_x[i] = x[i];
    __syncthreads();

    // Prefetch matrix values for step 0 (fully coalesced: warp = one 128B line)
    float m[8];
    {
        const float* M0 = core + (size_t)sh_x[0] * (DD * DD);
        #pragma unroll
        for (int k = 0; k < 8; ++k)
            m[k] = __ldg(M0 + (size_t)(row_base + k) * DD + col);
    }

    for (int s = 0; s < F; ++s) {
        // Stage this CTA's 256-element slice of v (sum the 4 row-quarter partials)
        if (tid < 256) {
            int gi = rb * 256 + tid;
            float vv;
            if (s == 0) {
                vv = left[gi];
            } else {
                int pb = (s + 1) & 1;
                vv = __ldcg(&g_vp[pb][0][gi]) + __ldcg(&g_vp[pb][1][gi])
                   + __ldcg(&g_vp[pb][2][gi]) + __ldcg(&g_vp[pb][3][gi]);
            }
            sh_v[tid] = vv;
        }
        __syncthreads();

        // Compute: acc over this thread's 8 rows (v broadcast from shared)
        float acc = 0.f;
        #pragma unroll
        for (int k = 0; k < 8; ++k)
            acc += m[k] * sh_v[w * 8 + k];

        // Prefetch next step's matrix values (hides L2 latency under
        // reduction + grid barrier)
        if (s + 1 < F) {
            const float* Mn = core + (size_t)sh_x[s + 1] * (DD * DD);
            #pragma unroll
            for (int k = 0; k < 8; ++k)
                m[k] = __ldg(Mn + (size_t)(row_base + k) * DD + col);
        }

        // Cross-warp reduction: 32 warps each hold one partial per column
        sh_p[w][lane] = acc;
        __syncthreads();
        if (w == 0) {
            float tot = 0.f;
            #pragma unroll
            for (int ww = 0; ww < 32; ++ww) tot += sh_p[ww][lane];
            g_vp[s & 1][rb][col] = tot;
            __threadfence();
        }

        grid_barrier();
    }

    // Final dot product: CTA 0 only, deterministic order
    if (blockIdx.x == 0) {
        int pb = (F - 1) & 1;
        float val = (__ldcg(&g_vp[pb][0][tid]) + __ldcg(&g_vp[pb][1][tid])
                   + __ldcg(&g_vp[pb][2][tid]) + __ldcg(&g_vp[pb][3][tid]))
                  * __ldg(right + tid);
        val += __shfl_xor_sync(0xffffffffu, val, 16);
        val += __shfl_xor_sync(0xffffffffu, val, 8);
        val += __shfl_xor_sync(0xffffffffu, val, 4);
        val += __shfl_xor_sync(0xffffffffu, val, 2);
        val += __shfl_xor_sync(0xffffffffu, val, 1);
        if (lane == 0) sh_r[w] = val;
        __syncthreads();
        if (tid == 0) {
            float tot = 0.f;
            #pragma unroll
            for (int ww = 0; ww < 32; ++ww) tot += sh_r[ww];
            out[0] = tot;
        }
    }
}

extern "C" void kernel_launch(void* const* d_in, const int* in_sizes, int n_in,
                              void* d_out, int out_size) {
    const int*   x     = (const int*)d_in[0];
    const float* core  = (const float*)d_in[1];
    const float* left  = (const float*)d_in[2];
    const float* right = (const float*)d_in[3];
    float* out = (float*)d_out;
    int F = in_sizes[0];

    tn_chain_kernel<<<NCTA, NTHREADS>>>(x, core, left, right, out, F);
}